// round 9
// baseline (speedup 1.0000x reference)
#include <cuda_runtime.h>

// B=4, C=80, M=16 fixed by the reference; N derived at runtime (76725 @640x640).
#define BB 4
#define CC 80
#define C4 20            // float4 per anchor row
#define MM 16
#define TILE 256         // anchors per block (one per thread in phase 1)
#define THREADS 256

#define IMG_W 640.0f
#define IMG_H 640.0f
#define EPS_F 1e-4f
#define BETA_F (1.0f / 9.0f)
#define LN2_F 0.6931471805599453f

__device__ float        g_cls_sum[BB];
__device__ float        g_reg_sum[BB];
__device__ int          g_pos[BB];
__device__ unsigned int g_count = 0;

// Packed focal-negative step for an element pair (x,y):
// acc2.{lo,hi} += p^2 * lg2(1-p).
__device__ __forceinline__ void foc2(float x, float y,
                                     unsigned long long& acc2,
                                     unsigned long long nones,   // {-1,-1}
                                     unsigned long long ones) {  // { 1, 1}
    unsigned long long v2, u2, l2, sq2;
    asm("mov.b64 %0, {%1, %2};" : "=l"(v2) : "f"(x), "f"(y));
    asm("fma.rn.f32x2 %0, %1, %2, %3;" : "=l"(u2) : "l"(v2), "l"(nones), "l"(ones));
    float ulo, uhi, llo, lhi;
    asm("mov.b64 {%0, %1}, %2;" : "=f"(ulo), "=f"(uhi) : "l"(u2));
    asm("lg2.approx.f32 %0, %1;" : "=f"(llo) : "f"(ulo));
    asm("lg2.approx.f32 %0, %1;" : "=f"(lhi) : "f"(uhi));
    asm("mov.b64 %0, {%1, %2};" : "=l"(l2) : "f"(llo), "f"(lhi));
    asm("mul.rn.f32x2 %0, %1, %2;" : "=l"(sq2) : "l"(v2), "l"(v2));
    asm("fma.rn.f32x2 %0, %1, %2, %3;" : "=l"(acc2) : "l"(sq2), "l"(l2), "l"(acc2));
}

__global__ void __launch_bounds__(THREADS, 4)
retina_fused_kernel(const float* __restrict__ cls,
                    const float* __restrict__ regs,
                    const float* __restrict__ anchors,
                    const float* __restrict__ annots,
                    float* __restrict__ out,
                    int N) {
    const int b   = blockIdx.y;
    const int n0  = blockIdx.x * TILE;
    const int tid = threadIdx.x;

    __shared__ float4 sbox[MM];
    __shared__ float2 sthr[MM];      // {0.4*area_g, 0.5*area_g}
    __shared__ float  scls[MM];
    __shared__ int    sanyv;
    __shared__ float  slab[TILE];
    __shared__ float  swred[8][3];

    // ---- Phase 0: issue wave-0 cls loads + anchor load FIRST (overlap everything) ----
    const int al = tid >> 2;        // 0..63
    const int lc = tid & 3;
    const long img = (long)b * N;
    // clamped global anchor indices for the 4 groups (OOB-safe, values gated later)
    const int nA = min(n0 + al,       N - 1);
    const int nB = min(n0 + al + 64,  N - 1);
    const int nC = min(n0 + al + 128, N - 1);
    const int nD = min(n0 + al + 192, N - 1);
    const float4* __restrict__ cf4 = reinterpret_cast<const float4*>(cls);
    const float4* __restrict__ pA = cf4 + (img + nA) * C4 + lc;
    const float4* __restrict__ pB = cf4 + (img + nB) * C4 + lc;
    const float4* __restrict__ pC = cf4 + (img + nC) * C4 + lc;
    const float4* __restrict__ pD = cf4 + (img + nD) * C4 + lc;

    float4 v0[5], v1[5];
#pragma unroll
    for (int it = 0; it < 5; it++) v0[it] = pA[it * 4];   // wave 0: unconditional
#pragma unroll
    for (int it = 0; it < 5; it++) v1[it] = pB[it * 4];

    const int n = n0 + tid;
    const float4 a4 = reinterpret_cast<const float4*>(anchors)[img + min(n, N - 1)];

    // GT preprocessing (zero invalid boxes -> their IoU is 0, can never win)
    if (tid < MM) {
        const float* g = annots + (b * MM + tid) * 5;
        float g0 = g[0], g1 = g[1], g2 = g[2], g3 = g[3], gc = g[4];
        const bool valid = (gc >= 0.0f);
        const unsigned bal = __ballot_sync(0x0000ffffu, valid);
        if (tid == 0) sanyv = (bal != 0u);
        if (!valid) { g0 = g1 = g2 = g3 = 0.0f; gc = 0.0f; }
        sbox[tid] = make_float4(g0, g1, g2, g3);
        const float ag = (g2 - g0) * (g3 - g1);
        sthr[tid] = make_float2(0.4f * ag, 0.5f * ag);
        scls[tid] = gc;
    }
    __syncthreads();

    // ---- Phase 1: threshold maxes (no division, no argmax in hot loop) ----
    float my_reg = 0.0f;
    float my_pos = 0.0f;
    float my_cor = 0.0f;
    {
        const float a0 = a4.x, a1 = a4.y, a2 = a4.z, a3 = a4.w;
        const bool inside = (a0 > 0.0f) && (a1 > 0.0f) && (a2 < IMG_W) && (a3 < IMG_H);
        const float area_a = (a2 - a0) * (a3 - a1);
        const float t04 = 0.4f * area_a;
        const float t05 = 0.5f * area_a;

        float m04 = -1e30f, m05 = -1e30f;
#pragma unroll
        for (int j = 0; j < MM; j++) {
            const float4 g  = sbox[j];
            const float2 th = sthr[j];
            const float lx = fmaxf(a0, g.x), ly = fmaxf(a1, g.y);
            const float rx = fminf(a2, g.z), ry = fminf(a3, g.w);
            const float wx = fmaxf(rx - lx, 0.0f), wy = fmaxf(ry - ly, 0.0f);
            const float num = wx * wy;
            // iou_j >= 0.4  <=>  1.4*num - 0.4*area_g >= 0.4*area_a
            m04 = fmaxf(m04, fmaf(num, 1.4f, -th.x));
            m05 = fmaxf(m05, fmaf(num, 1.5f, -th.y));
        }

        float label = (m04 < t04) ? 0.0f : -1.0f;
        const bool is_pos = (m05 > t05) && sanyv && inside && (n < N);
        if (!sanyv || !inside || n >= N) label = -1.0f;

        if (is_pos) {
            // rare path: exact argmax with the original tie ordering
            const long an = img + n;
            float cn = -1.0f, cd = 1.0f;
            int bidx = 0;
#pragma unroll
            for (int j = 0; j < MM; j++) {
                const float4 g = sbox[j];
                const float2 th = sthr[j];
                const float area_g = th.x * 2.5f;           // 0.4*ag / 0.4
                const float lx = fmaxf(a0, g.x), ly = fmaxf(a1, g.y);
                const float rx = fminf(a2, g.z), ry = fminf(a3, g.w);
                const float wx = fmaxf(rx - lx, 0.0f), wy = fmaxf(ry - ly, 0.0f);
                const float num = wx * wy;
                const float den = area_a + area_g - num;
                if (num * cd > cn * den) { cn = num; cd = den; bidx = j; }
            }
            label = scls[bidx] + 1.0f;

            const float4 g = sbox[bidx];
            const float aw = a2 - a0, ah = a3 - a1;
            const float acx = a0 + 0.5f * aw, acy = a1 + 0.5f * ah;
            const float gw = fmaxf(g.z - g.x, 1.0f);
            const float gh = fmaxf(g.w - g.y, 1.0f);
            const float gcx = g.x + 0.5f * gw, gcy = g.y + 0.5f * gh;
            const float t0 = ((gcx - acx) / aw) * 10.0f;
            const float t1 = ((gcy - acy) / ah) * 10.0f;
            const float t2 = __logf(gw / aw) * 5.0f;
            const float t3 = __logf(gh / ah) * 5.0f;

            const float4 r4 = reinterpret_cast<const float4*>(regs)[an];
            const float xs[4] = { fabsf(r4.x - t0), fabsf(r4.y - t1),
                                  fabsf(r4.z - t2), fabsf(r4.w - t3) };
#pragma unroll
            for (int k = 0; k < 4; k++) {
                const float x = xs[k];
                my_reg += (x < BETA_F) ? (0.5f * x * x / BETA_F) : (x - 0.5f * BETA_F);
            }
            my_pos = 1.0f;

            const int lp = (int)label - 1;
            const float pv = cls[an * CC + lp];
            const float p = fminf(fmaxf(pv, EPS_F), 1.0f - EPS_F);
            const float q = 1.0f - p;
            my_cor = 0.25f * q * q * (-__logf(p)) - 0.75f * pv * pv * (-__logf(1.0f - pv));
        }
        slab[tid] = label;
    }
    __syncthreads();

    // ---- Phase 2: wave-0 math (prefetched), wave-1 gated load + math ----
    unsigned long long ones, nones, acc2;
    {
        const float one = 1.0f, mone = -1.0f, zero = 0.0f;
        asm("mov.b64 %0, {%1, %1};" : "=l"(ones)  : "f"(one));
        asm("mov.b64 %0, {%1, %1};" : "=l"(nones) : "f"(mone));
        asm("mov.b64 %0, {%1, %1};" : "=l"(acc2)  : "f"(zero));
    }

    const bool uA = (slab[al]       >= 0.0f);
    const bool uB = (slab[al + 64]  >= 0.0f);
    const bool uC = (slab[al + 128] >= 0.0f);
    const bool uD = (slab[al + 192] >= 0.0f);

    if (uA) {
#pragma unroll
        for (int it = 0; it < 5; it++) {
            foc2(v0[it].x, v0[it].y, acc2, nones, ones);
            foc2(v0[it].z, v0[it].w, acc2, nones, ones);
        }
    }
    if (uB) {
#pragma unroll
        for (int it = 0; it < 5; it++) {
            foc2(v1[it].x, v1[it].y, acc2, nones, ones);
            foc2(v1[it].z, v1[it].w, acc2, nones, ones);
        }
    }

    // wave 1 (gated loads, reuse registers)
    if (uC) {
#pragma unroll
        for (int it = 0; it < 5; it++) v0[it] = pC[it * 4];
    }
    if (uD) {
#pragma unroll
        for (int it = 0; it < 5; it++) v1[it] = pD[it * 4];
    }
    if (uC) {
#pragma unroll
        for (int it = 0; it < 5; it++) {
            foc2(v0[it].x, v0[it].y, acc2, nones, ones);
            foc2(v0[it].z, v0[it].w, acc2, nones, ones);
        }
    }
    if (uD) {
#pragma unroll
        for (int it = 0; it < 5; it++) {
            foc2(v1[it].x, v1[it].y, acc2, nones, ones);
            foc2(v1[it].z, v1[it].w, acc2, nones, ones);
        }
    }

    float slo, shi;
    asm("mov.b64 {%0, %1}, %2;" : "=f"(slo), "=f"(shi) : "l"(acc2));
    float acc = fmaf(-0.75f * LN2_F, slo + shi, my_cor);

    // ---- Phase 3: warp shuffle reduce, one barrier, 3 atomics per block ----
#pragma unroll
    for (int o = 16; o; o >>= 1) {
        acc    += __shfl_down_sync(0xffffffffu, acc,    o);
        my_reg += __shfl_down_sync(0xffffffffu, my_reg, o);
        my_pos += __shfl_down_sync(0xffffffffu, my_pos, o);
    }
    const int wid = tid >> 5;
    if ((tid & 31) == 0) {
        swred[wid][0] = acc;
        swred[wid][1] = my_reg;
        swred[wid][2] = my_pos;
    }
    __syncthreads();
    if (tid == 0) {
        float c = 0.0f, r = 0.0f, p = 0.0f;
#pragma unroll
        for (int w = 0; w < 8; w++) {
            c += swred[w][0];
            r += swred[w][1];
            p += swred[w][2];
        }
        if (c != 0.0f) atomicAdd(&g_cls_sum[b], c);
        if (r != 0.0f) atomicAdd(&g_reg_sum[b], r);
        const int pi = (int)(p + 0.5f);
        if (pi) atomicAdd(&g_pos[b], pi);
    }

    // ---- Phase 4: last block finalizes + resets state for next replay ----
    __shared__ bool is_last;
    __threadfence();
    if (tid == 0) {
        const unsigned total = gridDim.x * gridDim.y;
        is_last = (atomicAdd(&g_count, 1u) == total - 1u);
    }
    __syncthreads();
    if (!is_last) return;

    if (tid == 0) {
        float cls_l = 0.0f, reg_l = 0.0f, nvalid = 0.0f;
#pragma unroll
        for (int bi = 0; bi < BB; bi++) {
            const float p = (float)g_pos[bi];
            if (p > 0.0f) {
                cls_l += g_cls_sum[bi] / p;
                reg_l += g_reg_sum[bi] / (4.0f * p);
                nvalid += 1.0f;
            }
            g_cls_sum[bi] = 0.0f;
            g_reg_sum[bi] = 0.0f;
            g_pos[bi] = 0;
        }
        nvalid = fmaxf(nvalid, 1.0f);
        out[0] = cls_l / nvalid;
        out[1] = reg_l / nvalid;
        g_count = 0;
    }
}

extern "C" void kernel_launch(void* const* d_in, const int* in_sizes, int n_in,
                              void* d_out, int out_size) {
    const float* cls     = (const float*)d_in[0];  // (B, N, C)
    const float* regs    = (const float*)d_in[1];  // (B, N, 4)
    const float* anchors = (const float*)d_in[2];  // (B, N, 4)
    const float* annots  = (const float*)d_in[3];  // (B, M, 5)

    const int N = in_sizes[1] / (BB * 4);
    const int numTiles = (N + TILE - 1) / TILE;

    dim3 grid(numTiles, BB);
    retina_fused_kernel<<<grid, THREADS>>>(cls, regs, anchors, annots,
                                           (float*)d_out, N);
}

// round 10
// speedup vs baseline: 1.5280x; 1.5280x over previous
#include <cuda_runtime.h>

// B=4, C=80, M=16 fixed by the reference; N derived at runtime (76725 @640x640).
#define BB 4
#define CC 80
#define C4 20            // float4 per anchor row
#define MM 16
#define TILE 256         // anchors per block (one per thread in phase 1)
#define THREADS 256

#define IMG_W 640.0f
#define IMG_H 640.0f
#define EPS_F 1e-4f
#define BETA_F (1.0f / 9.0f)
#define LN2_F 0.6931471805599453f

__device__ float        g_cls_sum[BB];
__device__ float        g_reg_sum[BB];
__device__ int          g_pos[BB];
__device__ unsigned int g_count = 0;

// Packed focal-negative step for an element pair (x,y): acc2 += p^2 * lg2(1-p).
__device__ __forceinline__ void foc2(float x, float y,
                                     unsigned long long& acc2,
                                     unsigned long long nones,   // {-1,-1}
                                     unsigned long long ones) {  // { 1, 1}
    unsigned long long v2, u2, l2, sq2;
    asm("mov.b64 %0, {%1, %2};" : "=l"(v2) : "f"(x), "f"(y));
    asm("fma.rn.f32x2 %0, %1, %2, %3;" : "=l"(u2) : "l"(v2), "l"(nones), "l"(ones));
    float ulo, uhi, llo, lhi;
    asm("mov.b64 {%0, %1}, %2;" : "=f"(ulo), "=f"(uhi) : "l"(u2));
    asm("lg2.approx.f32 %0, %1;" : "=f"(llo) : "f"(ulo));
    asm("lg2.approx.f32 %0, %1;" : "=f"(lhi) : "f"(uhi));
    asm("mov.b64 %0, {%1, %2};" : "=l"(l2) : "f"(llo), "f"(lhi));
    asm("mul.rn.f32x2 %0, %1, %2;" : "=l"(sq2) : "l"(v2), "l"(v2));
    asm("fma.rn.f32x2 %0, %1, %2, %3;" : "=l"(acc2) : "l"(sq2), "l"(l2), "l"(acc2));
}

__global__ void __launch_bounds__(THREADS, 4)
retina_fused_kernel(const float* __restrict__ cls,
                    const float* __restrict__ regs,
                    const float* __restrict__ anchors,
                    const float* __restrict__ annots,
                    float* __restrict__ out,
                    int N) {
    const int b    = blockIdx.y;
    const int n0   = blockIdx.x * TILE;
    const int tid  = threadIdx.x;
    const int lane = tid & 31;
    const int wrp  = tid >> 5;
    const long img = (long)b * N;

    __shared__ float4 sbox[MM];
    __shared__ float2 sthr[MM];      // {0.4*area_g, 0.5*area_g}
    __shared__ float  scls[MM];
    __shared__ int    sanyv;
    __shared__ float  swred[8][3];

    // GT preprocessing (zero invalid boxes -> their IoU is 0, can never win)
    if (tid < MM) {
        const float* g = annots + (b * MM + tid) * 5;
        float g0 = g[0], g1 = g[1], g2 = g[2], g3 = g[3], gc = g[4];
        const bool valid = (gc >= 0.0f);
        const unsigned bal = __ballot_sync(0x0000ffffu, valid);
        if (tid == 0) sanyv = (bal != 0u);
        if (!valid) { g0 = g1 = g2 = g3 = 0.0f; gc = 0.0f; }
        sbox[tid] = make_float4(g0, g1, g2, g3);
        const float ag = (g2 - g0) * (g3 - g1);
        sthr[tid] = make_float2(0.4f * ag, 0.5f * ag);
        scls[tid] = gc;
    }
    __syncthreads();   // the ONLY barrier before the final reduction

    // ---- Phase 1 (one anchor per thread): threshold maxes, label in register ----
    const int n = n0 + tid;
    float label  = -1.0f;
    float my_reg = 0.0f;
    float my_pos = 0.0f;
    float my_cor = 0.0f;
    {
        const float4 a4 = reinterpret_cast<const float4*>(anchors)[img + min(n, N - 1)];
        const float a0 = a4.x, a1 = a4.y, a2 = a4.z, a3 = a4.w;
        const bool inside = (a0 > 0.0f) && (a1 > 0.0f) && (a2 < IMG_W) && (a3 < IMG_H);
        const float area_a = (a2 - a0) * (a3 - a1);
        const float t04 = 0.4f * area_a;
        const float t05 = 0.5f * area_a;

        float m04 = -1e30f, m05 = -1e30f;
#pragma unroll
        for (int j = 0; j < MM; j++) {
            const float4 g  = sbox[j];
            const float2 th = sthr[j];
            const float lx = fmaxf(a0, g.x), ly = fmaxf(a1, g.y);
            const float rx = fminf(a2, g.z), ry = fminf(a3, g.w);
            const float wx = fmaxf(rx - lx, 0.0f), wy = fmaxf(ry - ly, 0.0f);
            const float num = wx * wy;
            // iou_j >= 0.4  <=>  1.4*num - 0.4*area_g >= 0.4*area_a
            m04 = fmaxf(m04, fmaf(num, 1.4f, -th.x));
            m05 = fmaxf(m05, fmaf(num, 1.5f, -th.y));
        }

        label = (m04 < t04) ? 0.0f : -1.0f;
        const bool is_pos = (m05 > t05) && sanyv && inside && (n < N);
        if (!sanyv || !inside || n >= N) label = -1.0f;

        if (is_pos) {
            // rare path: exact argmax with the original tie ordering
            const long an = img + n;
            float cn = -1.0f, cd = 1.0f;
            int bidx = 0;
#pragma unroll
            for (int j = 0; j < MM; j++) {
                const float4 g = sbox[j];
                const float area_g = sthr[j].x * 2.5f;
                const float lx = fmaxf(a0, g.x), ly = fmaxf(a1, g.y);
                const float rx = fminf(a2, g.z), ry = fminf(a3, g.w);
                const float wx = fmaxf(rx - lx, 0.0f), wy = fmaxf(ry - ly, 0.0f);
                const float num = wx * wy;
                const float den = area_a + area_g - num;
                if (num * cd > cn * den) { cn = num; cd = den; bidx = j; }
            }
            label = scls[bidx] + 1.0f;

            const float4 g = sbox[bidx];
            const float aw = a2 - a0, ah = a3 - a1;
            const float acx = a0 + 0.5f * aw, acy = a1 + 0.5f * ah;
            const float gw = fmaxf(g.z - g.x, 1.0f);
            const float gh = fmaxf(g.w - g.y, 1.0f);
            const float gcx = g.x + 0.5f * gw, gcy = g.y + 0.5f * gh;
            const float t0 = ((gcx - acx) / aw) * 10.0f;
            const float t1 = ((gcy - acy) / ah) * 10.0f;
            const float t2 = __logf(gw / aw) * 5.0f;
            const float t3 = __logf(gh / ah) * 5.0f;

            const float4 r4 = reinterpret_cast<const float4*>(regs)[an];
            const float xs[4] = { fabsf(r4.x - t0), fabsf(r4.y - t1),
                                  fabsf(r4.z - t2), fabsf(r4.w - t3) };
#pragma unroll
            for (int k = 0; k < 4; k++) {
                const float x = xs[k];
                my_reg += (x < BETA_F) ? (0.5f * x * x / BETA_F) : (x - 0.5f * BETA_F);
            }
            my_pos = 1.0f;

            const int lp = (int)label - 1;
            const float pv = cls[an * CC + lp];
            const float p = fminf(fmaxf(pv, EPS_F), 1.0f - EPS_F);
            const float q = 1.0f - p;
            my_cor = 0.25f * q * q * (-__logf(p)) - 0.75f * pv * pv * (-__logf(1.0f - pv));
        }
    }

    // ---- Label exchange within the warp (no block barrier!) ----
    const int ag = lane >> 2;                 // anchor group 0..7 within warp
    const float labA = __shfl_sync(0xffffffffu, label, ag);
    const float labB = __shfl_sync(0xffffffffu, label, ag + 8);
    const float labC = __shfl_sync(0xffffffffu, label, ag + 16);
    const float labD = __shfl_sync(0xffffffffu, label, ag + 24);
    const bool uA = (labA >= 0.0f);
    const bool uB = (labB >= 0.0f);
    const bool uC = (labC >= 0.0f);
    const bool uD = (labD >= 0.0f);

    // ---- Phase 2: warp-local sweep of its own 32 anchors, two 10-LDG waves ----
    const int abase = n0 + wrp * 32;          // warp's first anchor
    const float4* __restrict__ cf4 = reinterpret_cast<const float4*>(cls);
    const float4* __restrict__ pA = cf4 + (img + abase + ag) * C4 + (lane & 3);
    const float4* __restrict__ pB = pA + 8  * C4;
    const float4* __restrict__ pC = pA + 16 * C4;
    const float4* __restrict__ pD = pA + 24 * C4;

    unsigned long long ones, nones, acc2;
    {
        const float one = 1.0f, mone = -1.0f, zero = 0.0f;
        asm("mov.b64 %0, {%1, %1};" : "=l"(ones)  : "f"(one));
        asm("mov.b64 %0, {%1, %1};" : "=l"(nones) : "f"(mone));
        asm("mov.b64 %0, {%1, %1};" : "=l"(acc2)  : "f"(zero));
    }

    float4 v0[5], v1[5];
    if (uA) {
#pragma unroll
        for (int it = 0; it < 5; it++) v0[it] = pA[it * 4];
    }
    if (uB) {
#pragma unroll
        for (int it = 0; it < 5; it++) v1[it] = pB[it * 4];
    }
    if (uA) {
#pragma unroll
        for (int it = 0; it < 5; it++) {
            foc2(v0[it].x, v0[it].y, acc2, nones, ones);
            foc2(v0[it].z, v0[it].w, acc2, nones, ones);
        }
    }
    if (uB) {
#pragma unroll
        for (int it = 0; it < 5; it++) {
            foc2(v1[it].x, v1[it].y, acc2, nones, ones);
            foc2(v1[it].z, v1[it].w, acc2, nones, ones);
        }
    }
    if (uC) {
#pragma unroll
        for (int it = 0; it < 5; it++) v0[it] = pC[it * 4];
    }
    if (uD) {
#pragma unroll
        for (int it = 0; it < 5; it++) v1[it] = pD[it * 4];
    }
    if (uC) {
#pragma unroll
        for (int it = 0; it < 5; it++) {
            foc2(v0[it].x, v0[it].y, acc2, nones, ones);
            foc2(v0[it].z, v0[it].w, acc2, nones, ones);
        }
    }
    if (uD) {
#pragma unroll
        for (int it = 0; it < 5; it++) {
            foc2(v1[it].x, v1[it].y, acc2, nones, ones);
            foc2(v1[it].z, v1[it].w, acc2, nones, ones);
        }
    }

    float slo, shi;
    asm("mov.b64 {%0, %1}, %2;" : "=f"(slo), "=f"(shi) : "l"(acc2));
    float acc = fmaf(-0.75f * LN2_F, slo + shi, my_cor);

    // ---- Phase 3: warp shuffle reduce, one barrier, 3 atomics per block ----
#pragma unroll
    for (int o = 16; o; o >>= 1) {
        acc    += __shfl_down_sync(0xffffffffu, acc,    o);
        my_reg += __shfl_down_sync(0xffffffffu, my_reg, o);
        my_pos += __shfl_down_sync(0xffffffffu, my_pos, o);
    }
    if (lane == 0) {
        swred[wrp][0] = acc;
        swred[wrp][1] = my_reg;
        swred[wrp][2] = my_pos;
    }
    __syncthreads();
    if (tid == 0) {
        float c = 0.0f, r = 0.0f, p = 0.0f;
#pragma unroll
        for (int w = 0; w < 8; w++) {
            c += swred[w][0];
            r += swred[w][1];
            p += swred[w][2];
        }
        if (c != 0.0f) atomicAdd(&g_cls_sum[b], c);
        if (r != 0.0f) atomicAdd(&g_reg_sum[b], r);
        const int pi = (int)(p + 0.5f);
        if (pi) atomicAdd(&g_pos[b], pi);
    }

    // ---- Phase 4: last block finalizes + resets state for next replay ----
    __shared__ bool is_last;
    __threadfence();
    if (tid == 0) {
        const unsigned total = gridDim.x * gridDim.y;
        is_last = (atomicAdd(&g_count, 1u) == total - 1u);
    }
    __syncthreads();
    if (!is_last) return;

    if (tid == 0) {
        float cls_l = 0.0f, reg_l = 0.0f, nvalid = 0.0f;
#pragma unroll
        for (int bi = 0; bi < BB; bi++) {
            const float p = (float)g_pos[bi];
            if (p > 0.0f) {
                cls_l += g_cls_sum[bi] / p;
                reg_l += g_reg_sum[bi] / (4.0f * p);
                nvalid += 1.0f;
            }
            g_cls_sum[bi] = 0.0f;
            g_reg_sum[bi] = 0.0f;
            g_pos[bi] = 0;
        }
        nvalid = fmaxf(nvalid, 1.0f);
        out[0] = cls_l / nvalid;
        out[1] = reg_l / nvalid;
        g_count = 0;
    }
}

extern "C" void kernel_launch(void* const* d_in, const int* in_sizes, int n_in,
                              void* d_out, int out_size) {
    const float* cls     = (const float*)d_in[0];  // (B, N, C)
    const float* regs    = (const float*)d_in[1];  // (B, N, 4)
    const float* anchors = (const float*)d_in[2];  // (B, N, 4)
    const float* annots  = (const float*)d_in[3];  // (B, M, 5)

    const int N = in_sizes[1] / (BB * 4);
    const int numTiles = (N + TILE - 1) / TILE;

    dim3 grid(numTiles, BB);
    retina_fused_kernel<<<grid, THREADS>>>(cls, regs, anchors, annots,
                                           (float*)d_out, N);
}